// round 2
// baseline (speedup 1.0000x reference)
#include <cuda_runtime.h>
#include <math.h>

#define T_TOKENS 4096
#define D_DIM    1024
#define H_DIM    2048
#define E_NUM    8

// ---------------- scratch (device globals; no runtime allocation) ----------
__device__ float g_probs[T_TOKENS * E_NUM];      // softmax probs [T,E]
__device__ float g_topval[T_TOKENS];             // top-1 prob
__device__ int   g_count[E_NUM];                 // tokens per expert
__device__ int   g_toklist[E_NUM * T_TOKENS];    // token ids per expert
__device__ float g_h[T_TOKENS * H_DIM];          // hidden activations (32 MB)
__device__ float g_y[T_TOKENS * D_DIM];          // expert output * top_val (16 MB)

__device__ __forceinline__ float gelu_exact(float v) {
    return 0.5f * v * (1.0f + erff(v * 0.70710678118654752440f));
}

// ---------------- 0: zero counters ----------------
__global__ void zero_kernel() {
    if (threadIdx.x < E_NUM) g_count[threadIdx.x] = 0;
}

// ---------------- 1: gating ----------------
// one block per token; warp e computes logit e
__global__ void gate_kernel(const float* __restrict__ x,
                            const float* __restrict__ gw,
                            const float* __restrict__ gb) {
    int t    = blockIdx.x;
    int tid  = threadIdx.x;
    int warp = tid >> 5;
    int lane = tid & 31;
    const float* xr = x + (size_t)t * D_DIM;
    float s = 0.f;
    #pragma unroll 4
    for (int d = lane; d < D_DIM; d += 32)
        s += xr[d] * gw[d * E_NUM + warp];
    #pragma unroll
    for (int o = 16; o > 0; o >>= 1) s += __shfl_xor_sync(0xffffffffu, s, o);
    __shared__ float logits[E_NUM];
    if (lane == 0) logits[warp] = s + gb[warp];
    __syncthreads();
    if (tid == 0) {
        float mx = logits[0];
        #pragma unroll
        for (int e = 1; e < E_NUM; e++) mx = fmaxf(mx, logits[e]);
        float p[E_NUM], den = 0.f;
        #pragma unroll
        for (int e = 0; e < E_NUM; e++) { p[e] = expf(logits[e] - mx); den += p[e]; }
        float inv = 1.f / den;
        float best = -1.f; int bi = 0;
        #pragma unroll
        for (int e = 0; e < E_NUM; e++) {
            p[e] *= inv;
            g_probs[t * E_NUM + e] = p[e];
            if (p[e] > best) { best = p[e]; bi = e; }   // first-max wins (argmax semantics)
        }
        g_topval[t] = best;
        int slot = atomicAdd(&g_count[bi], 1);
        g_toklist[bi * T_TOKENS + slot] = t;
    }
}

// ---------------- 2: FFN layer 1  h = gelu(x_g @ w1[e] + b1[e]) ----------------
// gathered-A tiled sgemm: BM=BN=128, BK=8, 256 threads, 8x8 per thread
__global__ __launch_bounds__(256, 2)
void ffn1_kernel(const float* __restrict__ x,
                 const float* __restrict__ w1,
                 const float* __restrict__ b1) {
    const int e   = blockIdx.z;
    const int cnt = g_count[e];
    const int m0  = blockIdx.y * 128;
    if (m0 >= cnt) return;
    const int n0  = blockIdx.x * 128;
    const int* toks = g_toklist + e * T_TOKENS;
    const float* B  = w1 + (size_t)e * D_DIM * H_DIM;

    __shared__ float As[8][128];
    __shared__ float Bs[8][128];
    const int tid = threadIdx.x;

    // A-tile mapping: thread loads float4 of K for one gathered row
    const int a_m = tid >> 1;
    const int a_k = (tid & 1) * 4;
    int a_tok = (m0 + a_m < cnt) ? toks[m0 + a_m] : -1;

    // B-tile mapping: k = tid/32, n4 = (tid&31)*4 (coalesced)
    const int b_k = tid >> 5;
    const int b_n = (tid & 31) * 4;

    const int rm = (tid >> 4) * 8;
    const int rn = (tid & 15) * 8;
    float acc[8][8] = {};

    for (int k0 = 0; k0 < D_DIM; k0 += 8) {
        float4 av = make_float4(0.f, 0.f, 0.f, 0.f);
        if (a_tok >= 0)
            av = *(const float4*)(x + (size_t)a_tok * D_DIM + k0 + a_k);
        float4 bv = *(const float4*)(B + (size_t)(k0 + b_k) * H_DIM + n0 + b_n);
        __syncthreads();
        As[a_k + 0][a_m] = av.x;
        As[a_k + 1][a_m] = av.y;
        As[a_k + 2][a_m] = av.z;
        As[a_k + 3][a_m] = av.w;
        *(float4*)&Bs[b_k][b_n] = bv;
        __syncthreads();
        #pragma unroll
        for (int kk = 0; kk < 8; kk++) {
            float a[8], b[8];
            #pragma unroll
            for (int i = 0; i < 8; i++) a[i] = As[kk][rm + i];
            #pragma unroll
            for (int j = 0; j < 8; j++) b[j] = Bs[kk][rn + j];
            #pragma unroll
            for (int i = 0; i < 8; i++)
                #pragma unroll
                for (int j = 0; j < 8; j++)
                    acc[i][j] = fmaf(a[i], b[j], acc[i][j]);
        }
    }

    const float* bias = b1 + e * H_DIM + n0;
    #pragma unroll
    for (int i = 0; i < 8; i++) {
        int gm = m0 + rm + i;
        if (gm >= cnt) continue;
        int tok = toks[gm];
        float* hr = g_h + (size_t)tok * H_DIM + n0;
        #pragma unroll
        for (int j = 0; j < 8; j++) {
            float v = acc[i][j] + bias[rn + j];
            hr[rn + j] = gelu_exact(v);
        }
    }
}

// ---------------- 3: FFN layer 2  y = (h_g @ w2[e] + b2[e]) * top_val ----------------
__global__ __launch_bounds__(256, 2)
void ffn2_kernel(const float* __restrict__ w2,
                 const float* __restrict__ b2) {
    const int e   = blockIdx.z;
    const int cnt = g_count[e];
    const int m0  = blockIdx.y * 128;
    if (m0 >= cnt) return;
    const int n0  = blockIdx.x * 128;
    const int* toks = g_toklist + e * T_TOKENS;
    const float* B  = w2 + (size_t)e * H_DIM * D_DIM;

    __shared__ float As[8][128];
    __shared__ float Bs[8][128];
    const int tid = threadIdx.x;

    const int a_m = tid >> 1;
    const int a_k = (tid & 1) * 4;
    int a_tok = (m0 + a_m < cnt) ? toks[m0 + a_m] : -1;

    const int b_k = tid >> 5;
    const int b_n = (tid & 31) * 4;

    const int rm = (tid >> 4) * 8;
    const int rn = (tid & 15) * 8;
    float acc[8][8] = {};

    for (int k0 = 0; k0 < H_DIM; k0 += 8) {
        float4 av = make_float4(0.f, 0.f, 0.f, 0.f);
        if (a_tok >= 0)
            av = *(const float4*)(g_h + (size_t)a_tok * H_DIM + k0 + a_k);
        float4 bv = *(const float4*)(B + (size_t)(k0 + b_k) * D_DIM + n0 + b_n);
        __syncthreads();
        As[a_k + 0][a_m] = av.x;
        As[a_k + 1][a_m] = av.y;
        As[a_k + 2][a_m] = av.z;
        As[a_k + 3][a_m] = av.w;
        *(float4*)&Bs[b_k][b_n] = bv;
        __syncthreads();
        #pragma unroll
        for (int kk = 0; kk < 8; kk++) {
            float a[8], b[8];
            #pragma unroll
            for (int i = 0; i < 8; i++) a[i] = As[kk][rm + i];
            #pragma unroll
            for (int j = 0; j < 8; j++) b[j] = Bs[kk][rn + j];
            #pragma unroll
            for (int i = 0; i < 8; i++)
                #pragma unroll
                for (int j = 0; j < 8; j++)
                    acc[i][j] = fmaf(a[i], b[j], acc[i][j]);
        }
    }

    const float* bias = b2 + e * D_DIM + n0;
    #pragma unroll
    for (int i = 0; i < 8; i++) {
        int gm = m0 + rm + i;
        if (gm >= cnt) continue;
        int tok = toks[gm];
        float tv = g_topval[tok];
        float* yr = g_y + (size_t)tok * D_DIM + n0;
        #pragma unroll
        for (int j = 0; j < 8; j++) {
            float v = (acc[i][j] + bias[rn + j]) * tv;
            yr[rn + j] = v;
        }
    }
}

// ---------------- 4: residual + L2-normalize + gamma*sqrt(D) + gelu ----------------
__global__ void finalize_kernel(const float* __restrict__ x,
                                const float* __restrict__ gamma,
                                float* __restrict__ out) {
    const int t   = blockIdx.x;
    const int tid = threadIdx.x;
    const float* xr = x  + (size_t)t * D_DIM;
    const float* er = g_y + (size_t)t * D_DIM;
    float yv[4];
    float ss = 0.f;
    #pragma unroll
    for (int i = 0; i < 4; i++) {
        int d = i * 256 + tid;
        float v = xr[d] + er[d];
        yv[i] = v;
        ss += v * v;
    }
    __shared__ float red[256];
    red[tid] = ss;
    __syncthreads();
    #pragma unroll
    for (int o = 128; o > 0; o >>= 1) {
        if (tid < o) red[tid] += red[tid + o];
        __syncthreads();
    }
    float nrm   = sqrtf(red[0]);
    float scale = 32.0f / fmaxf(nrm, 1e-12f);   // sqrt(1024) = 32
    float* orow = out + (size_t)t * D_DIM;
    #pragma unroll
    for (int i = 0; i < 4; i++) {
        int d = i * 256 + tid;
        float v = yv[i] * scale * gamma[d];
        orow[d] = gelu_exact(v);
    }
}

// ---------------- 5: load-balance loss (deterministic tree reduction) ----------------
__global__ void loss_kernel(float* __restrict__ out, int out_size) {
    __shared__ float red[256];
    __shared__ float imp[E_NUM];
    const int tid = threadIdx.x;
    for (int e = 0; e < E_NUM; e++) {
        float s = 0.f;
        for (int t = tid; t < T_TOKENS; t += 256)
            s += g_probs[t * E_NUM + e];
        red[tid] = s;
        __syncthreads();
        #pragma unroll
        for (int o = 128; o > 0; o >>= 1) {
            if (tid < o) red[tid] += red[tid + o];
            __syncthreads();
        }
        if (tid == 0) imp[e] = red[0];
        __syncthreads();
    }
    if (tid == 0) {
        float sum = 0.f;
        #pragma unroll
        for (int e = 0; e < E_NUM; e++) sum += imp[e];
        float mean = sum / (float)E_NUM;
        float var = 0.f;
        #pragma unroll
        for (int e = 0; e < E_NUM; e++) {
            float dlt = imp[e] - mean;
            var += dlt * dlt;
        }
        var /= (float)(E_NUM - 1);              // ddof=1
        float loss = var / (mean * mean + 1e-10f);
        if (out_size > T_TOKENS * D_DIM)
            out[T_TOKENS * D_DIM] = loss;
    }
}

// ---------------- launch ----------------
extern "C" void kernel_launch(void* const* d_in, const int* in_sizes, int n_in,
                              void* d_out, int out_size) {
    const float* x     = (const float*)d_in[0];
    const float* gw    = (const float*)d_in[1];
    const float* gb    = (const float*)d_in[2];
    const float* w1    = (const float*)d_in[3];
    const float* b1    = (const float*)d_in[4];
    const float* w2    = (const float*)d_in[5];
    const float* b2    = (const float*)d_in[6];
    const float* gamma = (const float*)d_in[7];
    float* out = (float*)d_out;

    zero_kernel<<<1, 32>>>();
    gate_kernel<<<T_TOKENS, 256>>>(x, gw, gb);
    // worst case all tokens on one expert: 32 M-tiles of 128
    ffn1_kernel<<<dim3(H_DIM / 128, T_TOKENS / 128, E_NUM), 256>>>(x, w1, b1);
    ffn2_kernel<<<dim3(D_DIM / 128, T_TOKENS / 128, E_NUM), 256>>>(w2, b2);
    finalize_kernel<<<T_TOKENS, 256>>>(x, gamma, out);
    loss_kernel<<<1, 256>>>(out, out_size);
}

// round 3
// speedup vs baseline: 4.1078x; 4.1078x over previous
#include <cuda_runtime.h>
#include <cuda_bf16.h>
#include <math.h>
#include <stdint.h>

#define T_TOKENS 4096
#define D_DIM    1024
#define H_DIM    2048
#define E_NUM    8

// ---------------- scratch (device globals; no runtime allocation) ----------
__device__ float g_probs[T_TOKENS * E_NUM];
__device__ float g_topval[T_TOKENS];
__device__ int   g_count[E_NUM];
__device__ int   g_toklist[E_NUM * T_TOKENS];
__device__ __nv_bfloat16 g_xb[T_TOKENS * D_DIM];          // x in bf16 (8 MB)
__device__ __nv_bfloat16 g_w1b[E_NUM * D_DIM * H_DIM];    // 33.5 MB
__device__ __nv_bfloat16 g_w2b[E_NUM * H_DIM * D_DIM];    // 33.5 MB
__device__ __nv_bfloat16 g_hb[T_TOKENS * H_DIM];          // hidden bf16 (16 MB)
__device__ float g_y[T_TOKENS * D_DIM];                   // expert out * top_val (16 MB)

__device__ __forceinline__ float gelu_exact(float v) {
    return 0.5f * v * (1.0f + erff(v * 0.70710678118654752440f));
}

__device__ __forceinline__ uint32_t smem_u32(const void* p) {
    return (uint32_t)__cvta_generic_to_shared(p);
}

__device__ __forceinline__ void cp_async16(uint32_t dst, const void* src, int src_bytes) {
    asm volatile("cp.async.cg.shared.global [%0], [%1], 16, %2;\n"
                 :: "r"(dst), "l"(src), "r"(src_bytes));
}

__device__ __forceinline__ void ldsm_x4(uint32_t* r, uint32_t addr) {
    asm volatile("ldmatrix.sync.aligned.m8n8.x4.shared.b16 {%0,%1,%2,%3}, [%4];\n"
                 : "=r"(r[0]), "=r"(r[1]), "=r"(r[2]), "=r"(r[3]) : "r"(addr));
}

__device__ __forceinline__ void ldsm_x4_trans(uint32_t* r, uint32_t addr) {
    asm volatile("ldmatrix.sync.aligned.m8n8.x4.trans.shared.b16 {%0,%1,%2,%3}, [%4];\n"
                 : "=r"(r[0]), "=r"(r[1]), "=r"(r[2]), "=r"(r[3]) : "r"(addr));
}

__device__ __forceinline__ void mma_bf16(float* d, const uint32_t* a, uint32_t b0, uint32_t b1) {
    asm volatile("mma.sync.aligned.m16n8k16.row.col.f32.bf16.bf16.f32 "
                 "{%0,%1,%2,%3}, {%4,%5,%6,%7}, {%8,%9}, {%0,%1,%2,%3};\n"
                 : "+f"(d[0]), "+f"(d[1]), "+f"(d[2]), "+f"(d[3])
                 : "r"(a[0]), "r"(a[1]), "r"(a[2]), "r"(a[3]), "r"(b0), "r"(b1));
}

// ---------------- 0: zero counters ----------------
__global__ void zero_kernel() {
    if (threadIdx.x < E_NUM) g_count[threadIdx.x] = 0;
}

// ---------------- 0b: fp32 -> bf16 conversion ----------------
__global__ void convert_kernel(const float* __restrict__ src,
                               __nv_bfloat16* __restrict__ dst, int n) {
    int i = (blockIdx.x * blockDim.x + threadIdx.x) * 4;
    if (i < n) {
        float4 v = *(const float4*)(src + i);
        __nv_bfloat162* d = (__nv_bfloat162*)(dst + i);
        d[0] = __floats2bfloat162_rn(v.x, v.y);
        d[1] = __floats2bfloat162_rn(v.z, v.w);
    }
}

// ---------------- 1: gating ----------------
__global__ void gate_kernel(const float* __restrict__ x,
                            const float* __restrict__ gw,
                            const float* __restrict__ gb) {
    int t    = blockIdx.x;
    int tid  = threadIdx.x;
    int warp = tid >> 5;
    int lane = tid & 31;
    const float* xr = x + (size_t)t * D_DIM;
    float s = 0.f;
    #pragma unroll 4
    for (int d = lane; d < D_DIM; d += 32)
        s += xr[d] * gw[d * E_NUM + warp];
    #pragma unroll
    for (int o = 16; o > 0; o >>= 1) s += __shfl_xor_sync(0xffffffffu, s, o);
    __shared__ float logits[E_NUM];
    if (lane == 0) logits[warp] = s + gb[warp];
    __syncthreads();
    if (tid == 0) {
        float mx = logits[0];
        #pragma unroll
        for (int e = 1; e < E_NUM; e++) mx = fmaxf(mx, logits[e]);
        float p[E_NUM], den = 0.f;
        #pragma unroll
        for (int e = 0; e < E_NUM; e++) { p[e] = expf(logits[e] - mx); den += p[e]; }
        float inv = 1.f / den;
        float best = -1.f; int bi = 0;
        #pragma unroll
        for (int e = 0; e < E_NUM; e++) {
            p[e] *= inv;
            g_probs[t * E_NUM + e] = p[e];
            if (p[e] > best) { best = p[e]; bi = e; }
        }
        g_topval[t] = best;
        int slot = atomicAdd(&g_count[bi], 1);
        g_toklist[bi * T_TOKENS + slot] = t;
    }
}

// ---------------- 2/3: tensor-core gathered GEMM ----------------
#define BM 128
#define BN 128
#define BK 32
#define A_STRIDE 40    // padded bf16 row stride (80 B) -> conflict-free ldmatrix
#define B_STRIDE 136   // padded bf16 row stride (272 B) -> conflict-free ldmatrix

// EPI 0: h = gelu(acc + b1) -> g_hb (bf16).  EPI 1: y = (acc + b2)*top_val -> g_y (f32)
template<int KDIM, int NDIM, int EPI>
__global__ __launch_bounds__(256, 2)
void moe_gemm(const __nv_bfloat16* __restrict__ Aglob,
              const __nv_bfloat16* __restrict__ Wglob,
              const float* __restrict__ bias_glob) {
    const int e   = blockIdx.z;
    const int cnt = g_count[e];
    const int m0  = blockIdx.y * BM;
    if (m0 >= cnt) return;
    const int n0  = blockIdx.x * BN;
    const int* toks = g_toklist + e * T_TOKENS;
    const __nv_bfloat16* Bglob = Wglob + (size_t)e * KDIM * NDIM;
    const float* bias = bias_glob + e * NDIM;

    __shared__ __nv_bfloat16 As[2][BM][A_STRIDE];
    __shared__ __nv_bfloat16 Bs[2][BK][B_STRIDE];

    const int tid  = threadIdx.x;
    const int lane = tid & 31;
    const int warp = tid >> 5;
    const int wm   = warp >> 2;      // 0..1 -> 64-row slab
    const int wn   = warp & 3;       // 0..3 -> 32-col slab

    // A load mapping: row = tid>>1, two 16B units per thread
    const int a_row  = tid >> 1;
    const int a_u    = (tid & 1) * 2;
    const int gm_a   = m0 + a_row;
    const bool a_ok  = (gm_a < cnt);
    const int a_tok  = a_ok ? toks[gm_a] : 0;
    const __nv_bfloat16* a_src = Aglob + (size_t)a_tok * KDIM + a_u * 8;
    const int a_bytes = a_ok ? 16 : 0;

    // B load mapping: two 16B units per thread (tid and tid+256)
    const int b_row0 = tid >> 4;
    const int b_cu   = tid & 15;
    const int b_row1 = b_row0 + 16;
    const __nv_bfloat16* b_src0 = Bglob + (size_t)b_row0 * NDIM + n0 + b_cu * 8;
    const __nv_bfloat16* b_src1 = Bglob + (size_t)b_row1 * NDIM + n0 + b_cu * 8;

    uint32_t a_dst0[2], a_dst1[2], b_dst0[2], b_dst1[2];
    #pragma unroll
    for (int s = 0; s < 2; s++) {
        a_dst0[s] = smem_u32(&As[s][a_row][a_u * 8]);
        a_dst1[s] = smem_u32(&As[s][a_row][(a_u + 1) * 8]);
        b_dst0[s] = smem_u32(&Bs[s][b_row0][b_cu * 8]);
        b_dst1[s] = smem_u32(&Bs[s][b_row1][b_cu * 8]);
    }

    float acc[4][4][4];
    #pragma unroll
    for (int i = 0; i < 4; i++)
        #pragma unroll
        for (int j = 0; j < 4; j++)
            #pragma unroll
            for (int c = 0; c < 4; c++) acc[i][j][c] = 0.f;

    // prologue: stage 0
    cp_async16(a_dst0[0], a_src, a_bytes);
    cp_async16(a_dst1[0], a_src + 8, a_bytes);
    cp_async16(b_dst0[0], b_src0, 16);
    cp_async16(b_dst1[0], b_src1, 16);
    asm volatile("cp.async.commit_group;\n");

    const int NT = KDIM / BK;
    for (int kt = 0; kt < NT; kt++) {
        if (kt + 1 < NT) {
            const int koff = (kt + 1) * BK;
            const int buf  = (kt + 1) & 1;
            cp_async16(a_dst0[buf], a_src + koff, a_bytes);
            cp_async16(a_dst1[buf], a_src + koff + 8, a_bytes);
            cp_async16(b_dst0[buf], b_src0 + (size_t)koff * NDIM, 16);
            cp_async16(b_dst1[buf], b_src1 + (size_t)koff * NDIM, 16);
        }
        asm volatile("cp.async.commit_group;\n");
        asm volatile("cp.async.wait_group 1;\n");
        __syncthreads();

        const int buf = kt & 1;
        #pragma unroll
        for (int ks = 0; ks < 2; ks++) {
            uint32_t afr[4][4];
            #pragma unroll
            for (int mt = 0; mt < 4; mt++) {
                int row = wm * 64 + mt * 16 + (lane & 15);
                int col = ks * 16 + ((lane >> 4) << 3);
                ldsm_x4(afr[mt], smem_u32(&As[buf][row][col]));
            }
            uint32_t bfr[2][4];
            #pragma unroll
            for (int pr = 0; pr < 2; pr++) {
                int row = ks * 16 + (lane & 15);
                int col = wn * 32 + pr * 16 + ((lane >> 4) << 3);
                ldsm_x4_trans(bfr[pr], smem_u32(&Bs[buf][row][col]));
            }
            #pragma unroll
            for (int mt = 0; mt < 4; mt++)
                #pragma unroll
                for (int nt = 0; nt < 4; nt++) {
                    int pr = nt >> 1;
                    int hb = (nt & 1) * 2;
                    mma_bf16(acc[mt][nt], afr[mt], bfr[pr][hb], bfr[pr][hb + 1]);
                }
        }
        __syncthreads();
    }

    // epilogue
    #pragma unroll
    for (int mt = 0; mt < 4; mt++) {
        int gm0 = m0 + wm * 64 + mt * 16 + (lane >> 2);
        int gm1 = gm0 + 8;
        bool ok0 = gm0 < cnt, ok1 = gm1 < cnt;
        int tok0 = ok0 ? toks[gm0] : 0;
        int tok1 = ok1 ? toks[gm1] : 0;
        float tv0 = 0.f, tv1 = 0.f;
        if (EPI == 1) {
            tv0 = ok0 ? g_topval[tok0] : 0.f;
            tv1 = ok1 ? g_topval[tok1] : 0.f;
        }
        #pragma unroll
        for (int nt = 0; nt < 4; nt++) {
            int col = n0 + wn * 32 + nt * 8 + (lane & 3) * 2;
            float bv0 = bias[col], bv1 = bias[col + 1];
            float* a = acc[mt][nt];
            if (EPI == 0) {
                if (ok0) {
                    __nv_bfloat162 v = __floats2bfloat162_rn(
                        gelu_exact(a[0] + bv0), gelu_exact(a[1] + bv1));
                    *(__nv_bfloat162*)(g_hb + (size_t)tok0 * H_DIM + col) = v;
                }
                if (ok1) {
                    __nv_bfloat162 v = __floats2bfloat162_rn(
                        gelu_exact(a[2] + bv0), gelu_exact(a[3] + bv1));
                    *(__nv_bfloat162*)(g_hb + (size_t)tok1 * H_DIM + col) = v;
                }
            } else {
                if (ok0) {
                    float2 v = make_float2((a[0] + bv0) * tv0, (a[1] + bv1) * tv0);
                    *(float2*)(g_y + (size_t)tok0 * D_DIM + col) = v;
                }
                if (ok1) {
                    float2 v = make_float2((a[2] + bv0) * tv1, (a[3] + bv1) * tv1);
                    *(float2*)(g_y + (size_t)tok1 * D_DIM + col) = v;
                }
            }
        }
    }
}

// ---------------- 4: residual + L2-normalize + gamma*sqrt(D) + gelu ----------------
__global__ void finalize_kernel(const float* __restrict__ x,
                                const float* __restrict__ gamma,
                                float* __restrict__ out) {
    const int t   = blockIdx.x;
    const int tid = threadIdx.x;
    const float* xr = x  + (size_t)t * D_DIM;
    const float* er = g_y + (size_t)t * D_DIM;
    float yv[4];
    float ss = 0.f;
    #pragma unroll
    for (int i = 0; i < 4; i++) {
        int d = i * 256 + tid;
        float v = xr[d] + er[d];
        yv[i] = v;
        ss += v * v;
    }
    __shared__ float red[256];
    red[tid] = ss;
    __syncthreads();
    #pragma unroll
    for (int o = 128; o > 0; o >>= 1) {
        if (tid < o) red[tid] += red[tid + o];
        __syncthreads();
    }
    float nrm   = sqrtf(red[0]);
    float scale = 32.0f / fmaxf(nrm, 1e-12f);
    float* orow = out + (size_t)t * D_DIM;
    #pragma unroll
    for (int i = 0; i < 4; i++) {
        int d = i * 256 + tid;
        float v = yv[i] * scale * gamma[d];
        orow[d] = gelu_exact(v);
    }
}

// ---------------- 5: load-balance loss ----------------
__global__ void loss_kernel(float* __restrict__ out, int out_size) {
    __shared__ float red[256];
    __shared__ float imp[E_NUM];
    const int tid = threadIdx.x;
    for (int e = 0; e < E_NUM; e++) {
        float s = 0.f;
        for (int t = tid; t < T_TOKENS; t += 256)
            s += g_probs[t * E_NUM + e];
        red[tid] = s;
        __syncthreads();
        #pragma unroll
        for (int o = 128; o > 0; o >>= 1) {
            if (tid < o) red[tid] += red[tid + o];
            __syncthreads();
        }
        if (tid == 0) imp[e] = red[0];
        __syncthreads();
    }
    if (tid == 0) {
        float sum = 0.f;
        #pragma unroll
        for (int e = 0; e < E_NUM; e++) sum += imp[e];
        float mean = sum / (float)E_NUM;
        float var = 0.f;
        #pragma unroll
        for (int e = 0; e < E_NUM; e++) {
            float dlt = imp[e] - mean;
            var += dlt * dlt;
        }
        var /= (float)(E_NUM - 1);
        float loss = var / (mean * mean + 1e-10f);
        if (out_size > T_TOKENS * D_DIM)
            out[T_TOKENS * D_DIM] = loss;
    }
}

// ---------------- launch ----------------
extern "C" void kernel_launch(void* const* d_in, const int* in_sizes, int n_in,
                              void* d_out, int out_size) {
    const float* x     = (const float*)d_in[0];
    const float* gw    = (const float*)d_in[1];
    const float* gb    = (const float*)d_in[2];
    const float* w1    = (const float*)d_in[3];
    const float* b1    = (const float*)d_in[4];
    const float* w2    = (const float*)d_in[5];
    const float* b2    = (const float*)d_in[6];
    const float* gamma = (const float*)d_in[7];
    float* out = (float*)d_out;

    __nv_bfloat16 *xb, *w1b, *w2b, *hb;
    cudaGetSymbolAddress((void**)&xb,  g_xb);
    cudaGetSymbolAddress((void**)&w1b, g_w1b);
    cudaGetSymbolAddress((void**)&w2b, g_w2b);
    cudaGetSymbolAddress((void**)&hb,  g_hb);

    zero_kernel<<<1, 32>>>();
    {
        int n = T_TOKENS * D_DIM;
        convert_kernel<<<(n / 4 + 255) / 256, 256>>>(x, xb, n);
    }
    {
        int n = E_NUM * D_DIM * H_DIM;
        convert_kernel<<<(n / 4 + 255) / 256, 256>>>(w1, w1b, n);
        convert_kernel<<<(n / 4 + 255) / 256, 256>>>(w2, w2b, n);
    }
    gate_kernel<<<T_TOKENS, 256>>>(x, gw, gb);
    moe_gemm<D_DIM, H_DIM, 0><<<dim3(H_DIM / BN, T_TOKENS / BM, E_NUM), 256>>>(xb, w1b, b1);
    moe_gemm<H_DIM, D_DIM, 1><<<dim3(D_DIM / BN, T_TOKENS / BM, E_NUM), 256>>>(hb, w2b, b2);
    finalize_kernel<<<T_TOKENS, 256>>>(x, gamma, out);
    loss_kernel<<<1, 256>>>(out, out_size);
}